// round 5
// baseline (speedup 1.0000x reference)
#include <cuda_runtime.h>
#include <cstdint>

#define NB      8                        // batch elements per WARP (16 per CTA)
#define WDIM    256
#define HDIM    256
#define DPT     8
#define CHUNK   32                       // h-columns per chunk
#define NCHUNK  (HDIM / CHUNK)           // 8
#define NT      (DPT * NCHUNK)           // 64 total chunks
// Per-pair buffer: m[32][32] + b[32][32] floats = 2048 floats = 8KB
#define PAIR_BUF_FLOATS  2048
#define NBUF             3               // triple buffered
#define PAIR_FLOATS      (NBUF * PAIR_BUF_FLOATS)   // 6144 floats = 24KB
#define SMEM_BYTES       (8 * PAIR_FLOATS * 4)      // 8 pairs = 192 KB

typedef unsigned long long u64;

__device__ __forceinline__ void cp_async16(uint32_t smem_addr, const void* gptr) {
    asm volatile("cp.async.cg.shared.global [%0], [%1], 16;\n"
                 :: "r"(smem_addr), "l"(gptr));
}
__device__ __forceinline__ void cp_commit() {
    asm volatile("cp.async.commit_group;\n");
}
__device__ __forceinline__ u64 pack_dup(float x) {
    u64 r;
    asm("mov.b64 %0, {%1, %1};" : "=l"(r) : "f"(x));
    return r;
}
__device__ __forceinline__ u64 ffma2(u64 a, u64 b, u64 c) {
    u64 d;
    asm("fma.rn.f32x2 %0, %1, %2, %3;" : "=l"(d) : "l"(a), "l"(b), "l"(c));
    return d;
}
__device__ __forceinline__ void unpack2(u64 v, float& lo, float& hi) {
    asm("mov.b64 {%0, %1}, %2;" : "=f"(lo), "=f"(hi) : "l"(v));
}
__device__ __forceinline__ void lds_v2b64(uint32_t addr, u64& a, u64& b) {
    asm volatile("ld.shared.v2.b64 {%0, %1}, [%2];" : "=l"(a), "=l"(b) : "r"(addr));
}
__device__ __forceinline__ void pair_bar(int id) {
    asm volatile("bar.sync %0, 64;" :: "r"(id) : "memory");
}

__global__ __launch_bounds__(512, 1)
void dpm_kernel(const float* __restrict__ val,
                const float* __restrict__ M1, const float* __restrict__ B1,
                const float* __restrict__ M2, const float* __restrict__ B2,
                float* __restrict__ out)
{
    extern __shared__ float smem[];
    __shared__ float red[16][NB];
    __shared__ float q_s[16];

    const int tid    = threadIdx.x;
    const int wid    = tid >> 5;          // 0..15
    const int lane   = tid & 31;
    const int pair   = wid & 7;           // row group: rows 32*pair..32*pair+31
    const int team   = wid >> 3;          // 0: batches 0-7, 1: batches 8-15
    const int batch0 = blockIdx.x * 16;
    const int branch = blockIdx.y;

    const float* __restrict__ Mb = branch ? M2 : M1;
    const float* __restrict__ Bb = branch ? B2 : B1;

    const uint32_t sbase  = (uint32_t)__cvta_generic_to_shared(smem);
    const uint32_t pslice = sbase + pair * (PAIR_FLOATS * 4);

    u64 qq[NB];     // (q_i, q_i) packed; this warp's 8 batches
#pragma unroll
    for (int i = 0; i < NB; i++) qq[i] = pack_dup(val[batch0 + team * NB + i]);

    // Issue this warp's half of chunk t (team 0: M slice, team 1: B slice)
    // for rows [32*pair, 32*pair+32) into buffer t%3.
    auto issue = [&](int t) {
        const int d = t >> 3, c = t & 7;
        const float* src = (team == 0 ? Mb : Bb)
                         + d * (WDIM * HDIM) + pair * 32 * HDIM + c * CHUNK;
        const uint32_t so = pslice + (t % NBUF) * (PAIR_BUF_FLOATS * 4)
                                   + team * (1024 * 4);
#pragma unroll
        for (int i = 0; i < 8; i++) {      // 8 float4 per thread
            const int e4 = i * 32 + lane;  // 0..255 across warp
            const int r  = e4 >> 3;        // 8 float4 per 32-col row
            const int c4 = e4 & 7;
            cp_async16(so + (uint32_t)(r * 32 + c4 * 4) * 4,
                       src + r * HDIM + c4 * 4);
        }
        cp_commit();
    };

    // Prologue: prefetch chunks 0 and 1.
    issue(0);
    issue(1);

    for (int d = 0; d < DPT; d++) {
        float acc[NB];
#pragma unroll
        for (int i = 0; i < NB; i++) acc[i] = __int_as_float(0xff800000); // -inf

        for (int c = 0; c < NCHUNK; c++) {
            const int t = d * NCHUNK + c;

            // 1. wait for own half of chunk t
            if (t < NT - 1) asm volatile("cp.async.wait_group 1;\n");
            else            asm volatile("cp.async.wait_group 0;\n");
            // 2. pair barrier: partner's half landed AND partner finished
            //    reading buffer (t+2)%3 (its chunk t-1 compute precedes its
            //    chunk-t wait in program order).
            pair_bar(pair + 1);
            // 3. refill the retired buffer
            if (t + 2 < NT) issue(t + 2);

            // 4. compute chunk t: lane owns row 32*pair+lane; 4 cols per step
            //    via LDS.128; lane-rotated group order keeps LDS conflict-free.
            const uint32_t base_m = pslice + (t % NBUF) * (PAIR_BUF_FLOATS * 4)
                                           + lane * 32 * 4;
            const uint32_t base_b = base_m + 1024 * 4;
#pragma unroll
            for (int cc = 0; cc < CHUNK / 4; cc++) {       // 8 steps of 4 cols
                const uint32_t cp = ((cc + lane) & 7) * 16;  // bytes
                u64 m01, m23, b01, b23;
                lds_v2b64(base_m + cp, m01, m23);
                lds_v2b64(base_b + cp, b01, b23);
#pragma unroll
                for (int i = 0; i < NB; i++) {
                    u64 s01 = ffma2(qq[i], m01, b01);
                    u64 s23 = ffma2(qq[i], m23, b23);
                    float a, b2, e, f;
                    unpack2(s01, a, b2);
                    unpack2(s23, e, f);
                    acc[i] = fmaxf(acc[i], fmaxf(fmaxf(a, b2), fmaxf(e, f)));
                }
            }
        }

        // min over w: shfl-min within warp (32 rows), then across this team's
        // 8 warps via smem.
#pragma unroll
        for (int i = 0; i < NB; i++) {
            float v = acc[i];
#pragma unroll
            for (int o = 16; o > 0; o >>= 1)
                v = fminf(v, __shfl_xor_sync(0xffffffffu, v, o));
            if (lane == 0) red[wid][i] = v;
        }
        __syncthreads();
        if (tid < 16) {
            const int tm = tid >> 3;            // team of this batch slot
            const int bi = tid & 7;             // batch index within team
            float v = red[tm * 8 + 0][bi];
#pragma unroll
            for (int w = 1; w < 8; w++) v = fminf(v, red[tm * 8 + w][bi]);
            q_s[tid] = v;
        }
        __syncthreads();
#pragma unroll
        for (int i = 0; i < NB; i++) qq[i] = pack_dup(q_s[team * NB + i]);
    }

    if (tid < 16)
        out[branch * 1024 + batch0 + tid] = q_s[tid];
}

extern "C" void kernel_launch(void* const* d_in, const int* in_sizes, int n_in,
                              void* d_out, int out_size)
{
    const float* val = (const float*)d_in[0];
    const float* M1  = (const float*)d_in[1];
    const float* B1  = (const float*)d_in[2];
    const float* M2  = (const float*)d_in[3];
    const float* B2  = (const float*)d_in[4];
    float* out = (float*)d_out;

    cudaFuncSetAttribute(dpm_kernel,
                         cudaFuncAttributeMaxDynamicSharedMemorySize, SMEM_BYTES);

    dim3 grid(1024 / 16, 2);   // 64 batch tiles x 2 branches = 128 CTAs
    dpm_kernel<<<grid, 512, SMEM_BYTES>>>(val, M1, B1, M2, B2, out);
}